// round 7
// baseline (speedup 1.0000x reference)
#include <cuda_runtime.h>
#include <cstdint>

#define B_N   32768
#define C_INN 14
#define NN    52
#define H1D   64
#define H2D   128
#define FDIM  (NN*H2D)   // 6656
#define EPSB  1e-5f
#define SPB   8
#define NKT   (FDIM/32)  // 208 k-tiles for K3

// ---------------- scratch ----------------------------------------------------
__device__ float d_W01[H2D * C_INN];
__device__ float d_b01[H2D];
__device__ float d_Y[(size_t)B_N * NN * H2D];
__device__ float d_f[(size_t)B_N * H1D];
__device__ float d_sum1[NN], d_sq1[NN];
__device__ float d_sum2[H1D], d_sq2[H1D];
__device__ float d_a1[NN], d_c1[NN];
__device__ float d_a2[H1D], d_c2[H1D];

#define TF32R(o, f) asm("cvt.rna.tf32.f32 %0, %1;" : "=r"(o) : "f"(f))

__device__ __forceinline__ void mma_tf32(float c[4],
                                         uint32_t a0, uint32_t a1, uint32_t a2, uint32_t a3,
                                         uint32_t b0, uint32_t b1) {
    asm volatile(
        "mma.sync.aligned.m16n8k8.row.col.f32.tf32.tf32.f32 "
        "{%0,%1,%2,%3}, {%4,%5,%6,%7}, {%8,%9}, {%0,%1,%2,%3};"
        : "+f"(c[0]), "+f"(c[1]), "+f"(c[2]), "+f"(c[3])
        : "r"(a0), "r"(a1), "r"(a2), "r"(a3), "r"(b0), "r"(b1));
}

// ---------------- tiny kernels -----------------------------------------------
__global__ void kinit() {
    int t = threadIdx.x;
    if (t < NN)  { d_sum1[t] = 0.f; d_sq1[t] = 0.f; }
    if (t < H1D) { d_sum2[t] = 0.f; d_sq2[t] = 0.f; }
}
__global__ void kprep(const float* __restrict__ w0, const float* __restrict__ b0,
                      const float* __restrict__ w1, const float* __restrict__ b1) {
    int l = threadIdx.x;
    if (l >= H2D) return;
    float bb = b1[l];
    for (int m = 0; m < H1D; m++) bb = fmaf(w1[l*H1D + m], b0[m], bb);
    d_b01[l] = bb;
    for (int j = 0; j < C_INN; j++) {
        float s = 0.f;
        for (int m = 0; m < H1D; m++) s = fmaf(w1[l*H1D + m], w0[m*C_INN + j], s);
        d_W01[l*C_INN + j] = s;
    }
}
__global__ void k2(const float* __restrict__ g1, const float* __restrict__ be1) {
    int t = threadIdx.x;
    if (t < NN) {
        float inv = 1.f / ((float)B_N * (float)H2D);
        float mu  = d_sum1[t] * inv;
        float var = d_sq1[t] * inv - mu * mu;
        float a   = g1[t] * rsqrtf(var + EPSB);
        d_a1[t] = a; d_c1[t] = be1[t] - mu * a;
    }
}
__global__ void k4(const float* __restrict__ g2, const float* __restrict__ be2) {
    int t = threadIdx.x;
    if (t < H1D) {
        float inv = 1.f / (float)B_N;
        float mu  = d_sum2[t] * inv;
        float var = d_sq2[t] * inv - mu * mu;
        float a   = g2[t] * rsqrtf(var + EPSB);
        d_a2[t] = a; d_c2[t] = be2[t] - mu * a;
    }
}

// ---------------- K1: stage1 tf32 mma -> Ht; stage2 tf32 mma -> Y -------------
// dyn smem float offsets:
#define HT_OFF   0                       // Ht[128][72] | stage[64][132] alias
#define WCP_OFF  (128*72)                // wcp_r[64][68]
#define XS_OFF   (WCP_OFF + 64*68)       // Xs[64][18]  ([c][j], j-pad zeroed)
#define BC_OFF   (XS_OFF + 64*18)        // [64]
#define K1_SMEM_FLOATS (BC_OFF + 64)
#define K1_SMEM_BYTES  (K1_SMEM_FLOATS * 4)

__global__ __launch_bounds__(256)
void k1mma(const float* __restrict__ x, const float* __restrict__ wc,
           const float* __restrict__ bc) {
    extern __shared__ __align__(16) float sm[];
    const int t = threadIdx.x;
    const int w = t >> 5, lane = t & 31;
    const int gid = lane >> 2, tig = lane & 3;
    const int lr0 = w * 16 + gid, lr1 = lr0 + 8;   // l-rows owned by this thread

    // ---- one-time fills ----
    // wcp_r[o][kk]: permuted + tf32-rounded wc, zero pad (stage-2 B operand)
    for (int i = t; i < 64 * 64; i += 256) {
        int o = i >> 6, kk = i & 63;
        int m = kk & 7;
        int src_c = (kk & ~7) + (m >> 1) + ((m & 1) << 2);
        float v = 0.f;
        if (o < NN && src_c < NN) v = wc[o * NN + src_c];
        uint32_t r; TF32R(r, v);
        sm[WCP_OFF + o * 68 + kk] = __uint_as_float(r);
    }
    // Xs zero-fill (per-sample fill only touches j<14, n<52)
    for (int i = t; i < 64 * 18; i += 256) sm[XS_OFF + i] = 0.f;
    if (t < 64)  sm[BC_OFF + t] = (t < NN) ? bc[t] : 0.f;

    // ---- hoisted per-thread constants ----
    // W01 A-fragments (tf32): A[l][j], rows lr0/lr1, K=16 padded
    uint32_t wf[2][4];
    #pragma unroll
    for (int ks = 0; ks < 2; ks++) {
        int j0 = ks * 8 + tig, j1 = j0 + 4;
        float v0 = d_W01[lr0 * C_INN + j0];                    // j0 <= 11 < 14
        float v1 = d_W01[lr1 * C_INN + j0];
        float v2 = (j1 < C_INN) ? d_W01[lr0 * C_INN + j1] : 0.f;
        float v3 = (j1 < C_INN) ? d_W01[lr1 * C_INN + j1] : 0.f;
        TF32R(wf[ks][0], v0); TF32R(wf[ks][1], v1);
        TF32R(wf[ks][2], v2); TF32R(wf[ks][3], v3);
    }
    const float bias0 = d_b01[lr0], bias1 = d_b01[lr1];
    __syncthreads();

    float sqs[8], sqq[8];
    #pragma unroll
    for (int i = 0; i < 8; i++) { sqs[i] = 0.f; sqq[i] = 0.f; }

    const size_t base = (size_t)blockIdx.x * SPB;
    for (int sp = 0; sp < SPB; sp++) {
        const size_t b = base + sp;
        // ---- load X: Xs[n][j] = x[b][j][n] (coalesced read, transposed STS) --
        const float* xb = x + b * (C_INN * NN);
        for (int i = t; i < C_INN * NN; i += 256) {
            int j = i / NN, n = i - j * NN;
            sm[XS_OFF + n * 18 + j] = xb[i];
        }
        __syncthreads();   // Xs ready; also: prev readout done before Ht writes

        // ---- stage 1 (tf32 mma): Ht[l][c] = relu(W01 @ X^T + b01) ----
        {
            float acc1[8][4];
            #pragma unroll
            for (int nt = 0; nt < 8; nt++)
                #pragma unroll
                for (int a = 0; a < 4; a++) acc1[nt][a] = 0.f;
            #pragma unroll
            for (int ks = 0; ks < 2; ks++) {
                #pragma unroll
                for (int nt = 0; nt < 8; nt++) {
                    int brow = nt * 8 + gid;
                    uint32_t b0 = __float_as_uint(sm[XS_OFF + brow * 18 + ks * 8 + tig]);
                    uint32_t b1 = __float_as_uint(sm[XS_OFF + brow * 18 + ks * 8 + tig + 4]);
                    mma_tf32(acc1[nt], wf[ks][0], wf[ks][1], wf[ks][2], wf[ks][3], b0, b1);
                }
            }
            // epilogue: +bias, relu, tf32-round, guard c>=NN to zero, STS.64
            #pragma unroll
            for (int nt = 0; nt < 8; nt++) {
                int c0 = nt * 8 + tig * 2;      // even
                float h0 = fmaxf(acc1[nt][0] + bias0, 0.f);
                float h1 = fmaxf(acc1[nt][1] + bias0, 0.f);
                float h2 = fmaxf(acc1[nt][2] + bias1, 0.f);
                float h3 = fmaxf(acc1[nt][3] + bias1, 0.f);
                if (c0 >= NN) { h0 = h1 = h2 = h3 = 0.f; }
                uint32_t r0_, r1_, r2_, r3_;
                TF32R(r0_, h0); TF32R(r1_, h1); TF32R(r2_, h2); TF32R(r3_, h3);
                float2 p0 = { __uint_as_float(r0_), __uint_as_float(r1_) };
                float2 p1 = { __uint_as_float(r2_), __uint_as_float(r3_) };
                *(float2*)&sm[HT_OFF + lr0 * 72 + c0] = p0;
                *(float2*)&sm[HT_OFF + lr1 * 72 + c0] = p1;
            }
        }
        __syncthreads();   // Ht ready

        // ---- stage 2 (tf32 mma): Yt[l][o] = Ht[l][c] @ wc^T ----
        float acc2[8][4];
        #pragma unroll
        for (int nt = 0; nt < 8; nt++)
            #pragma unroll
            for (int a = 0; a < 4; a++) acc2[nt][a] = 0.f;
        #pragma unroll
        for (int ks = 0; ks < 8; ks++) {
            const int kc = ks * 8 + tig;
            uint32_t a0 = __float_as_uint(sm[HT_OFF + lr0 * 72 + kc]);
            uint32_t a1 = __float_as_uint(sm[HT_OFF + lr1 * 72 + kc]);
            uint32_t a2 = __float_as_uint(sm[HT_OFF + lr0 * 72 + kc + 4]);
            uint32_t a3 = __float_as_uint(sm[HT_OFF + lr1 * 72 + kc + 4]);
            #pragma unroll
            for (int nt = 0; nt < 8; nt++) {
                float2 bp = *(const float2*)&sm[WCP_OFF + (nt * 8 + gid) * 68 + ks * 8 + tig * 2];
                mma_tf32(acc2[nt], a0, a1, a2, a3,
                         __float_as_uint(bp.x), __float_as_uint(bp.y));
            }
        }
        __syncthreads();   // all Ht reads done before stage overwrite (alias)

        // ---- epilogue 2: +bc, transpose into stage[o][132] ----
        #pragma unroll
        for (int nt = 0; nt < 8; nt++) {
            int o0 = nt * 8 + tig * 2;
            float b0v = sm[BC_OFF + o0], b1v = sm[BC_OFF + o0 + 1];
            sm[HT_OFF + o0 * 132 + lr0]       = acc2[nt][0] + b0v;
            sm[HT_OFF + (o0 + 1) * 132 + lr0] = acc2[nt][1] + b1v;
            sm[HT_OFF + o0 * 132 + lr1]       = acc2[nt][2] + b0v;
            sm[HT_OFF + (o0 + 1) * 132 + lr1] = acc2[nt][3] + b1v;
        }
        __syncthreads();   // stage ready

        // ---- readout: coalesced Y store + bn1 partials ----
        float* yb = d_Y + b * FDIM;
        #pragma unroll
        for (int i = 0; i < 8; i++) {
            int o = w * 8 + i;
            if (o < NN) {
                float4 v = *(const float4*)&sm[HT_OFF + o * 132 + lane * 4];
                *(float4*)&yb[o * 128 + lane * 4] = v;
                sqs[i] += v.x + v.y + v.z + v.w;
                sqq[i] = fmaf(v.x, v.x, sqq[i]);
                sqq[i] = fmaf(v.y, v.y, sqq[i]);
                sqq[i] = fmaf(v.z, v.z, sqq[i]);
                sqq[i] = fmaf(v.w, v.w, sqq[i]);
            }
        }
    }

    // ---- bn1 stats ----
    #pragma unroll
    for (int i = 0; i < 8; i++) {
        float s = sqs[i], q = sqq[i];
        #pragma unroll
        for (int d = 16; d >= 1; d >>= 1) {
            s += __shfl_xor_sync(0xffffffffu, s, d);
            q += __shfl_xor_sync(0xffffffffu, q, d);
        }
        int o = w * 8 + i;
        if (lane == 0 && o < NN) {
            atomicAdd(&d_sum1[o], s);
            atomicAdd(&d_sq1[o], q);
        }
    }
}

// ---------------- K3: tf32 mma.sync GEMM, double-buffered --------------------
// dyn smem floats: As0[128][36] @0, As1 @4608, Bs0[64][36] @9216, Bs1 @11520
#define K3A0 0
#define K3A1 4608
#define K3B0 9216
#define K3B1 11520
#define K3_SMEM_BYTES ((11520 + 64*36) * 4)   // 55296

__global__ __launch_bounds__(256)
void k3mma(const float* __restrict__ wf1, const float* __restrict__ bf1) {
    extern __shared__ __align__(16) float sm[];
    __shared__ float a1_s[NN], c1_s[NN];
    float* stage = sm;   // [128][65] = 8320 floats, aliases As0+

    const int t = threadIdx.x;
    const int w = t >> 5, lane = t & 31;
    const int gid = lane >> 2, tig = lane & 3;
    if (t < NN) { a1_s[t] = d_a1[t]; c1_s[t] = d_c1[t]; }
    __syncthreads();

    const size_t b0 = (size_t)blockIdx.x * 128;
    const int am = t >> 1, ah = t & 1;
    const float* Arow = d_Y + (b0 + am) * FDIM + ah * 16;
    const int bn = t >> 2, bq = t & 3;
    const float* Brow = wf1 + (size_t)bn * FDIM + bq * 8;

    const int aoff[2] = { K3A0, K3A1 };
    const int boff[2] = { K3B0, K3B1 };

    float acc[8][4];
    #pragma unroll
    for (int nt = 0; nt < 8; nt++)
        #pragma unroll
        for (int i = 0; i < 4; i++) acc[nt][i] = 0.f;

    const int arow_lo = w * 16 + gid;
    const int arow_hi = arow_lo + 8;

    float4 aR[4], bR[2];

    // helper: LDG tile k0 into regs
    #define K3_LDG(k0) do { \
        _Pragma("unroll") \
        for (int i = 0; i < 4; i++) aR[i] = *(const float4*)(Arow + (k0) + i * 4); \
        _Pragma("unroll") \
        for (int i = 0; i < 2; i++) bR[i] = *(const float4*)(Brow + (k0) + i * 4); \
    } while (0)

    // helper: STS regs (tile k0) into buffer s with bn1+relu+tf32 (A) / tf32 (B)
    #define K3_STS(s, k0) do { \
        const int _o = (k0) >> 7; \
        const float _a1 = a1_s[_o], _c1 = c1_s[_o]; \
        _Pragma("unroll") \
        for (int i = 0; i < 4; i++) { \
            float4 v = aR[i]; \
            uint32_t r0_, r1_, r2_, r3_; \
            TF32R(r0_, fmaxf(fmaf(_a1, v.x, _c1), 0.f)); \
            TF32R(r1_, fmaxf(fmaf(_a1, v.y, _c1), 0.f)); \
            TF32R(r2_, fmaxf(fmaf(_a1, v.z, _c1), 0.f)); \
            TF32R(r3_, fmaxf(fmaf(_a1, v.w, _c1), 0.f)); \
            float4 sv = { __uint_as_float(r0_), __uint_as_float(r1_), \
                          __uint_as_float(r2_), __uint_as_float(r3_) }; \
            *(float4*)&sm[aoff[s] + am * 36 + ah * 16 + i * 4] = sv; \
        } \
        _Pragma("unroll") \
        for (int i = 0; i < 2; i++) { \
            float4 v = bR[i]; \
            uint32_t r0_, r1_, r2_, r3_; \
            TF32R(r0_, v.x); TF32R(r1_, v.y); TF32R(r2_, v.z); TF32R(r3_, v.w); \
            float4 sv = { __uint_as_float(r0_), __uint_as_float(r1_), \
                          __uint_as_float(r2_), __uint_as_float(r3_) }; \
            *(float4*)&sm[boff[s] + bn * 36 + bq * 8 + i * 4] = sv; \
        } \
    } while (0)

    // pipeline prologue
    K3_LDG(0);
    K3_STS(0, 0);
    K3_LDG(32);
    __syncthreads();

    for (int it = 0; it < NKT; it++) {
        const int cur = it & 1;
        // STS next tile (regs hold it+1) into other buffer; overlaps MMA issue
        if (it + 1 < NKT) K3_STS(cur ^ 1, (it + 1) * 32);
        // prefetch tile it+2
        if (it + 2 < NKT) K3_LDG((it + 2) * 32);
        // consume current buffer
        const int ab = aoff[cur], bb = boff[cur];
        #pragma unroll
        for (int ks = 0; ks < 4; ks++) {
            const int kc = ks * 8 + tig;
            uint32_t a0 = __float_as_uint(sm[ab + arow_lo * 36 + kc]);
            uint32_t a1 = __float_as_uint(sm[ab + arow_hi * 36 + kc]);
            uint32_t a2 = __float_as_uint(sm[ab + arow_lo * 36 + kc + 4]);
            uint32_t a3 = __float_as_uint(sm[ab + arow_hi * 36 + kc + 4]);
            #pragma unroll
            for (int nt = 0; nt < 8; nt++) {
                const int brow = nt * 8 + gid;
                uint32_t bb0 = __float_as_uint(sm[bb + brow * 36 + kc]);
                uint32_t bb1 = __float_as_uint(sm[bb + brow * 36 + kc + 4]);
                mma_tf32(acc[nt], a0, a1, a2, a3, bb0, bb1);
            }
        }
        __syncthreads();
    }

    // epilogue: +bf1, store d_f, stage for bn2 stats
    #pragma unroll
    for (int nt = 0; nt < 8; nt++) {
        const int n0 = nt * 8 + tig * 2;
        const float bf0 = __ldg(bf1 + n0), bf1v = __ldg(bf1 + n0 + 1);
        float v0 = acc[nt][0] + bf0, v1 = acc[nt][1] + bf1v;
        float v2 = acc[nt][2] + bf0, v3 = acc[nt][3] + bf1v;
        *(float2*)&d_f[(b0 + arow_lo) * H1D + n0] = make_float2(v0, v1);
        *(float2*)&d_f[(b0 + arow_hi) * H1D + n0] = make_float2(v2, v3);
        stage[arow_lo * 65 + n0]     = v0;
        stage[arow_lo * 65 + n0 + 1] = v1;
        stage[arow_hi * 65 + n0]     = v2;
        stage[arow_hi * 65 + n0 + 1] = v3;
    }
    __syncthreads();
    if (t < H1D) {
        float s = 0.f, q = 0.f;
        #pragma unroll 4
        for (int r = 0; r < 128; r++) {
            float v = stage[r * 65 + t];
            s += v; q = fmaf(v, v, q);
        }
        atomicAdd(&d_sum2[t], s);
        atomicAdd(&d_sq2[t], q);
    }
}

// ---------------- K5 ----------------------------------------------------------
__global__ void k5(const float* __restrict__ wf2, const float* __restrict__ bf2,
                   float* __restrict__ out) {
    const int t = threadIdx.x;
    const int w = t >> 5, l = t & 31;
    const size_t b = (size_t)blockIdx.x * 8 + w;
    float f0 = d_f[b * H1D + l];
    float f1 = d_f[b * H1D + 32 + l];
    float z0 = fmaxf(fmaf(d_a2[l], f0, d_c2[l]), 0.f);
    float z1 = fmaxf(fmaf(d_a2[32 + l], f1, d_c2[32 + l]), 0.f);
    float p0 = fmaf(z0, wf2[l],      z1 * wf2[32 + l]);
    float p1 = fmaf(z0, wf2[64 + l], z1 * wf2[96 + l]);
    #pragma unroll
    for (int d = 16; d >= 1; d >>= 1) {
        p0 += __shfl_xor_sync(0xffffffffu, p0, d);
        p1 += __shfl_xor_sync(0xffffffffu, p1, d);
    }
    if (l == 0) {
        out[b * 2 + 0] = p0 + bf2[0];
        out[b * 2 + 1] = p1 + bf2[1];
    }
}

// ---------------- launch -------------------------------------------------------
extern "C" void kernel_launch(void* const* d_in, const int* in_sizes, int n_in,
                              void* d_out, int out_size) {
    const float* x   = (const float*)d_in[0];
    const float* w0  = (const float*)d_in[1];
    const float* b0  = (const float*)d_in[2];
    const float* w1  = (const float*)d_in[3];
    const float* b1  = (const float*)d_in[4];
    const float* wc  = (const float*)d_in[5];
    const float* bc  = (const float*)d_in[6];
    const float* g1  = (const float*)d_in[7];
    const float* be1 = (const float*)d_in[8];
    const float* wf1 = (const float*)d_in[9];
    const float* bf1 = (const float*)d_in[10];
    const float* g2  = (const float*)d_in[11];
    const float* be2 = (const float*)d_in[12];
    const float* wf2 = (const float*)d_in[13];
    const float* bf2 = (const float*)d_in[14];
    float* out = (float*)d_out;

    cudaFuncSetAttribute(k1mma, cudaFuncAttributeMaxDynamicSharedMemorySize, K1_SMEM_BYTES);
    cudaFuncSetAttribute(k3mma, cudaFuncAttributeMaxDynamicSharedMemorySize, K3_SMEM_BYTES);

    kinit<<<1, 128>>>();
    kprep<<<1, 128>>>(w0, b0, w1, b1);
    k1mma<<<B_N / SPB, 256, K1_SMEM_BYTES>>>(x, wc, bc);
    k2<<<1, 64>>>(g1, be1);
    k3mma<<<B_N / 128, 256, K3_SMEM_BYTES>>>(wf1, bf1);
    k4<<<1, 64>>>(g2, be2);
    k5<<<B_N / 8, 256>>>(wf2, bf2, out);
}

// round 8
// speedup vs baseline: 1.0475x; 1.0475x over previous
#include <cuda_runtime.h>
#include <cstdint>

#define B_N   32768
#define C_INN 14
#define NN    52
#define H1D   64
#define H2D   128
#define FDIM  (NN*H2D)   // 6656
#define EPSB  1e-5f
#define SPB   8
#define NCHUNK 4
#define KC    (FDIM/NCHUNK)     // 1664 floats per chunk
#define NKT_C (KC/32)           // 52 k-tiles per chunk

// ---------------- scratch ----------------------------------------------------
__device__ float d_W01[H2D * C_INN];
__device__ float d_b01[H2D];
__device__ float d_Y[(size_t)B_N * NN * H2D];
__device__ float d_f[(size_t)B_N * H1D];
__device__ float d_sum1[NN], d_sq1[NN];
__device__ float d_sum2[H1D], d_sq2[H1D];
__device__ float d_a1[NN], d_c1[NN];
__device__ float d_a2[H1D], d_c2[H1D];

#define TF32R(o, f) asm("cvt.rna.tf32.f32 %0, %1;" : "=r"(o) : "f"(f))

__device__ __forceinline__ void mma_tf32(float c[4],
                                         uint32_t a0, uint32_t a1, uint32_t a2, uint32_t a3,
                                         uint32_t b0, uint32_t b1) {
    asm volatile(
        "mma.sync.aligned.m16n8k8.row.col.f32.tf32.tf32.f32 "
        "{%0,%1,%2,%3}, {%4,%5,%6,%7}, {%8,%9}, {%0,%1,%2,%3};"
        : "+f"(c[0]), "+f"(c[1]), "+f"(c[2]), "+f"(c[3])
        : "r"(a0), "r"(a1), "r"(a2), "r"(a3), "r"(b0), "r"(b1));
}

// ---------------- tiny kernels -----------------------------------------------
__global__ void kinit() {
    int t = threadIdx.x;
    if (t < NN)  { d_sum1[t] = 0.f; d_sq1[t] = 0.f; }
    if (t < H1D) { d_sum2[t] = 0.f; d_sq2[t] = 0.f; }
}
__global__ void kprep(const float* __restrict__ w0, const float* __restrict__ b0,
                      const float* __restrict__ w1, const float* __restrict__ b1) {
    int l = threadIdx.x;
    if (l >= H2D) return;
    float bb = b1[l];
    for (int m = 0; m < H1D; m++) bb = fmaf(w1[l*H1D + m], b0[m], bb);
    d_b01[l] = bb;
    for (int j = 0; j < C_INN; j++) {
        float s = 0.f;
        for (int m = 0; m < H1D; m++) s = fmaf(w1[l*H1D + m], w0[m*C_INN + j], s);
        d_W01[l*C_INN + j] = s;
    }
}
__global__ void k2(const float* __restrict__ g1, const float* __restrict__ be1) {
    int t = threadIdx.x;
    if (t < NN) {
        float inv = 1.f / ((float)B_N * (float)H2D);
        float mu  = d_sum1[t] * inv;
        float var = d_sq1[t] * inv - mu * mu;
        float a   = g1[t] * rsqrtf(var + EPSB);
        d_a1[t] = a; d_c1[t] = be1[t] - mu * a;
    }
}
__global__ void k4(const float* __restrict__ g2, const float* __restrict__ be2) {
    int t = threadIdx.x;
    if (t < H1D) {
        float inv = 1.f / (float)B_N;
        float mu  = d_sum2[t] * inv;
        float var = d_sq2[t] * inv - mu * mu;
        float a   = g2[t] * rsqrtf(var + EPSB);
        d_a2[t] = a; d_c2[t] = be2[t] - mu * a;
    }
}
// init d_f[b][j] = bf1[j] (atomic accumulation base for split-K fc1)
__global__ void kzerof(const float* __restrict__ bf1) {
    size_t i = (size_t)blockIdx.x * 256 + threadIdx.x;
    d_f[i] = bf1[i & 63];
}
// bn2 stats from completed d_f
__global__ void k3stats() {
    __shared__ float rs[2][4][64];
    const int t = threadIdx.x;
    const int col = t & 63, sub = t >> 6;
    const size_t r0 = (size_t)blockIdx.x * 128 + sub * 32;
    float s = 0.f, q = 0.f;
    #pragma unroll 4
    for (int i = 0; i < 32; i++) {
        float v = d_f[(r0 + i) * H1D + col];
        s += v; q = fmaf(v, v, q);
    }
    rs[0][sub][col] = s; rs[1][sub][col] = q;
    __syncthreads();
    if (sub == 0) {
        s = rs[0][0][col] + rs[0][1][col] + rs[0][2][col] + rs[0][3][col];
        q = rs[1][0][col] + rs[1][1][col] + rs[1][2][col] + rs[1][3][col];
        atomicAdd(&d_sum2[col], s);
        atomicAdd(&d_sq2[col], q);
    }
}

// ---------------- K1: stage1 tf32 mma -> Ht; stage2 tf32 mma -> Y -------------
#define HT_OFF   0                       // Ht[128][72] | stage[64][132] alias
#define WCP_OFF  (128*72)                // wcp_r[64][68]
#define XS_OFF   (WCP_OFF + 64*68)       // Xs[64][18]
#define BC_OFF   (XS_OFF + 64*18)        // [64]
#define K1_SMEM_FLOATS (BC_OFF + 64)
#define K1_SMEM_BYTES  (K1_SMEM_FLOATS * 4)

__global__ __launch_bounds__(256)
void k1mma(const float* __restrict__ x, const float* __restrict__ wc,
           const float* __restrict__ bc) {
    extern __shared__ __align__(16) float sm[];
    const int t = threadIdx.x;
    const int w = t >> 5, lane = t & 31;
    const int gid = lane >> 2, tig = lane & 3;
    const int lr0 = w * 16 + gid, lr1 = lr0 + 8;

    for (int i = t; i < 64 * 64; i += 256) {
        int o = i >> 6, kk = i & 63;
        int m = kk & 7;
        int src_c = (kk & ~7) + (m >> 1) + ((m & 1) << 2);
        float v = 0.f;
        if (o < NN && src_c < NN) v = wc[o * NN + src_c];
        uint32_t r; TF32R(r, v);
        sm[WCP_OFF + o * 68 + kk] = __uint_as_float(r);
    }
    for (int i = t; i < 64 * 18; i += 256) sm[XS_OFF + i] = 0.f;
    if (t < 64)  sm[BC_OFF + t] = (t < NN) ? bc[t] : 0.f;

    uint32_t wf[2][4];
    #pragma unroll
    for (int ks = 0; ks < 2; ks++) {
        int j0 = ks * 8 + tig, j1 = j0 + 4;
        float v0 = d_W01[lr0 * C_INN + j0];
        float v1 = d_W01[lr1 * C_INN + j0];
        float v2 = (j1 < C_INN) ? d_W01[lr0 * C_INN + j1] : 0.f;
        float v3 = (j1 < C_INN) ? d_W01[lr1 * C_INN + j1] : 0.f;
        TF32R(wf[ks][0], v0); TF32R(wf[ks][1], v1);
        TF32R(wf[ks][2], v2); TF32R(wf[ks][3], v3);
    }
    const float bias0 = d_b01[lr0], bias1 = d_b01[lr1];
    __syncthreads();

    float sqs[8], sqq[8];
    #pragma unroll
    for (int i = 0; i < 8; i++) { sqs[i] = 0.f; sqq[i] = 0.f; }

    const size_t base = (size_t)blockIdx.x * SPB;
    for (int sp = 0; sp < SPB; sp++) {
        const size_t b = base + sp;
        const float* xb = x + b * (C_INN * NN);
        for (int i = t; i < C_INN * NN; i += 256) {
            int j = i / NN, n = i - j * NN;
            sm[XS_OFF + n * 18 + j] = xb[i];
        }
        __syncthreads();

        {
            float acc1[8][4];
            #pragma unroll
            for (int nt = 0; nt < 8; nt++)
                #pragma unroll
                for (int a = 0; a < 4; a++) acc1[nt][a] = 0.f;
            #pragma unroll
            for (int ks = 0; ks < 2; ks++) {
                #pragma unroll
                for (int nt = 0; nt < 8; nt++) {
                    int brow = nt * 8 + gid;
                    uint32_t b0 = __float_as_uint(sm[XS_OFF + brow * 18 + ks * 8 + tig]);
                    uint32_t b1 = __float_as_uint(sm[XS_OFF + brow * 18 + ks * 8 + tig + 4]);
                    mma_tf32(acc1[nt], wf[ks][0], wf[ks][1], wf[ks][2], wf[ks][3], b0, b1);
                }
            }
            #pragma unroll
            for (int nt = 0; nt < 8; nt++) {
                int c0 = nt * 8 + tig * 2;
                float h0 = fmaxf(acc1[nt][0] + bias0, 0.f);
                float h1 = fmaxf(acc1[nt][1] + bias0, 0.f);
                float h2 = fmaxf(acc1[nt][2] + bias1, 0.f);
                float h3 = fmaxf(acc1[nt][3] + bias1, 0.f);
                if (c0 >= NN) { h0 = h1 = h2 = h3 = 0.f; }
                uint32_t r0_, r1_, r2_, r3_;
                TF32R(r0_, h0); TF32R(r1_, h1); TF32R(r2_, h2); TF32R(r3_, h3);
                float2 p0 = { __uint_as_float(r0_), __uint_as_float(r1_) };
                float2 p1 = { __uint_as_float(r2_), __uint_as_float(r3_) };
                *(float2*)&sm[HT_OFF + lr0 * 72 + c0] = p0;
                *(float2*)&sm[HT_OFF + lr1 * 72 + c0] = p1;
            }
        }
        __syncthreads();

        float acc2[8][4];
        #pragma unroll
        for (int nt = 0; nt < 8; nt++)
            #pragma unroll
            for (int a = 0; a < 4; a++) acc2[nt][a] = 0.f;
        #pragma unroll
        for (int ks = 0; ks < 8; ks++) {
            const int kc = ks * 8 + tig;
            uint32_t a0 = __float_as_uint(sm[HT_OFF + lr0 * 72 + kc]);
            uint32_t a1 = __float_as_uint(sm[HT_OFF + lr1 * 72 + kc]);
            uint32_t a2 = __float_as_uint(sm[HT_OFF + lr0 * 72 + kc + 4]);
            uint32_t a3 = __float_as_uint(sm[HT_OFF + lr1 * 72 + kc + 4]);
            #pragma unroll
            for (int nt = 0; nt < 8; nt++) {
                float2 bp = *(const float2*)&sm[WCP_OFF + (nt * 8 + gid) * 68 + ks * 8 + tig * 2];
                mma_tf32(acc2[nt], a0, a1, a2, a3,
                         __float_as_uint(bp.x), __float_as_uint(bp.y));
            }
        }
        __syncthreads();

        #pragma unroll
        for (int nt = 0; nt < 8; nt++) {
            int o0 = nt * 8 + tig * 2;
            float b0v = sm[BC_OFF + o0], b1v = sm[BC_OFF + o0 + 1];
            sm[HT_OFF + o0 * 132 + lr0]       = acc2[nt][0] + b0v;
            sm[HT_OFF + (o0 + 1) * 132 + lr0] = acc2[nt][1] + b1v;
            sm[HT_OFF + o0 * 132 + lr1]       = acc2[nt][2] + b0v;
            sm[HT_OFF + (o0 + 1) * 132 + lr1] = acc2[nt][3] + b1v;
        }
        __syncthreads();

        float* yb = d_Y + b * FDIM;
        #pragma unroll
        for (int i = 0; i < 8; i++) {
            int o = w * 8 + i;
            if (o < NN) {
                float4 v = *(const float4*)&sm[HT_OFF + o * 132 + lane * 4];
                *(float4*)&yb[o * 128 + lane * 4] = v;
                sqs[i] += v.x + v.y + v.z + v.w;
                sqq[i] = fmaf(v.x, v.x, sqq[i]);
                sqq[i] = fmaf(v.y, v.y, sqq[i]);
                sqq[i] = fmaf(v.z, v.z, sqq[i]);
                sqq[i] = fmaf(v.w, v.w, sqq[i]);
            }
        }
    }

    #pragma unroll
    for (int i = 0; i < 8; i++) {
        float s = sqs[i], q = sqq[i];
        #pragma unroll
        for (int d = 16; d >= 1; d >>= 1) {
            s += __shfl_xor_sync(0xffffffffu, s, d);
            q += __shfl_xor_sync(0xffffffffu, q, d);
        }
        int o = w * 8 + i;
        if (lane == 0 && o < NN) {
            atomicAdd(&d_sum1[o], s);
            atomicAdd(&d_sq1[o], q);
        }
    }
}

// ---------------- K3: tf32 mma GEMM, split-K x4, atomic accumulate ------------
#define K3A0 0
#define K3A1 4608
#define K3B0 9216
#define K3B1 11520
#define K3_SMEM_BYTES ((11520 + 64*36) * 4)   // 55296

__global__ __launch_bounds__(256)
void k3mma(const float* __restrict__ wf1) {
    extern __shared__ __align__(16) float sm[];
    __shared__ float a1_s[NN], c1_s[NN];

    const int t = threadIdx.x;
    const int w = t >> 5, lane = t & 31;
    const int gid = lane >> 2, tig = lane & 3;
    if (t < NN) { a1_s[t] = d_a1[t]; c1_s[t] = d_c1[t]; }
    __syncthreads();

    const size_t b0 = (size_t)blockIdx.x * 128;
    const int chunk = blockIdx.y;
    const int kbase = chunk * KC;
    const int obase = chunk * (NN / NCHUNK);    // 13 o per chunk

    const int am = t >> 1, ah = t & 1;
    const float* Arow = d_Y + (b0 + am) * FDIM + kbase + ah * 16;
    const int bn = t >> 2, bq = t & 3;
    const float* Brow = wf1 + (size_t)bn * FDIM + kbase + bq * 8;

    const int aoff[2] = { K3A0, K3A1 };
    const int boff[2] = { K3B0, K3B1 };

    float acc[8][4];
    #pragma unroll
    for (int nt = 0; nt < 8; nt++)
        #pragma unroll
        for (int i = 0; i < 4; i++) acc[nt][i] = 0.f;

    const int arow_lo = w * 16 + gid;
    const int arow_hi = arow_lo + 8;

    float4 aR[4], bR[2];

    #define K3_LDG(k0) do { \
        _Pragma("unroll") \
        for (int i = 0; i < 4; i++) aR[i] = *(const float4*)(Arow + (k0) + i * 4); \
        _Pragma("unroll") \
        for (int i = 0; i < 2; i++) bR[i] = *(const float4*)(Brow + (k0) + i * 4); \
    } while (0)

    #define K3_STS(s, k0) do { \
        const int _o = obase + ((k0) >> 7); \
        const float _a1 = a1_s[_o], _c1 = c1_s[_o]; \
        _Pragma("unroll") \
        for (int i = 0; i < 4; i++) { \
            float4 v = aR[i]; \
            uint32_t r0_, r1_, r2_, r3_; \
            TF32R(r0_, fmaxf(fmaf(_a1, v.x, _c1), 0.f)); \
            TF32R(r1_, fmaxf(fmaf(_a1, v.y, _c1), 0.f)); \
            TF32R(r2_, fmaxf(fmaf(_a1, v.z, _c1), 0.f)); \
            TF32R(r3_, fmaxf(fmaf(_a1, v.w, _c1), 0.f)); \
            float4 sv = { __uint_as_float(r0_), __uint_as_float(r1_), \
                          __uint_as_float(r2_), __uint_as_float(r3_) }; \
            *(float4*)&sm[aoff[s] + am * 36 + ah * 16 + i * 4] = sv; \
        } \
        _Pragma("unroll") \
        for (int i = 0; i < 2; i++) { \
            float4 v = bR[i]; \
            uint32_t r0_, r1_, r2_, r3_; \
            TF32R(r0_, v.x); TF32R(r1_, v.y); TF32R(r2_, v.z); TF32R(r3_, v.w); \
            float4 sv = { __uint_as_float(r0_), __uint_as_float(r1_), \
                          __uint_as_float(r2_), __uint_as_float(r3_) }; \
            *(float4*)&sm[boff[s] + bn * 36 + bq * 8 + i * 4] = sv; \
        } \
    } while (0)

    K3_LDG(0);
    K3_STS(0, 0);
    K3_LDG(32);
    __syncthreads();

    for (int it = 0; it < NKT_C; it++) {
        const int cur = it & 1;
        if (it + 1 < NKT_C) K3_STS(cur ^ 1, (it + 1) * 32);
        if (it + 2 < NKT_C) K3_LDG((it + 2) * 32);
        const int ab = aoff[cur], bb = boff[cur];
        #pragma unroll
        for (int ks = 0; ks < 4; ks++) {
            const int kc = ks * 8 + tig;
            uint32_t a0 = __float_as_uint(sm[ab + arow_lo * 36 + kc]);
            uint32_t a1 = __float_as_uint(sm[ab + arow_hi * 36 + kc]);
            uint32_t a2 = __float_as_uint(sm[ab + arow_lo * 36 + kc + 4]);
            uint32_t a3 = __float_as_uint(sm[ab + arow_hi * 36 + kc + 4]);
            #pragma unroll
            for (int nt = 0; nt < 8; nt++) {
                const int brow = nt * 8 + gid;
                uint32_t bb0 = __float_as_uint(sm[bb + brow * 36 + kc]);
                uint32_t bb1 = __float_as_uint(sm[bb + brow * 36 + kc + 4]);
                mma_tf32(acc[nt], a0, a1, a2, a3, bb0, bb1);
            }
        }
        __syncthreads();
    }

    // epilogue: atomic-accumulate partial fc1 sums into d_f (base = bf1)
    #pragma unroll
    for (int nt = 0; nt < 8; nt++) {
        const int n0 = nt * 8 + tig * 2;
        float* f_lo = d_f + (b0 + arow_lo) * H1D + n0;
        float* f_hi = d_f + (b0 + arow_hi) * H1D + n0;
        atomicAdd(f_lo,     acc[nt][0]);
        atomicAdd(f_lo + 1, acc[nt][1]);
        atomicAdd(f_hi,     acc[nt][2]);
        atomicAdd(f_hi + 1, acc[nt][3]);
    }
}

// ---------------- K5 ----------------------------------------------------------
__global__ void k5(const float* __restrict__ wf2, const float* __restrict__ bf2,
                   float* __restrict__ out) {
    const int t = threadIdx.x;
    const int w = t >> 5, l = t & 31;
    const size_t b = (size_t)blockIdx.x * 8 + w;
    float f0 = d_f[b * H1D + l];
    float f1 = d_f[b * H1D + 32 + l];
    float z0 = fmaxf(fmaf(d_a2[l], f0, d_c2[l]), 0.f);
    float z1 = fmaxf(fmaf(d_a2[32 + l], f1, d_c2[32 + l]), 0.f);
    float p0 = fmaf(z0, wf2[l],      z1 * wf2[32 + l]);
    float p1 = fmaf(z0, wf2[64 + l], z1 * wf2[96 + l]);
    #pragma unroll
    for (int d = 16; d >= 1; d >>= 1) {
        p0 += __shfl_xor_sync(0xffffffffu, p0, d);
        p1 += __shfl_xor_sync(0xffffffffu, p1, d);
    }
    if (l == 0) {
        out[b * 2 + 0] = p0 + bf2[0];
        out[b * 2 + 1] = p1 + bf2[1];
    }
}

// ---------------- launch -------------------------------------------------------
extern "C" void kernel_launch(void* const* d_in, const int* in_sizes, int n_in,
                              void* d_out, int out_size) {
    const float* x   = (const float*)d_in[0];
    const float* w0  = (const float*)d_in[1];
    const float* b0  = (const float*)d_in[2];
    const float* w1  = (const float*)d_in[3];
    const float* b1  = (const float*)d_in[4];
    const float* wc  = (const float*)d_in[5];
    const float* bc  = (const float*)d_in[6];
    const float* g1  = (const float*)d_in[7];
    const float* be1 = (const float*)d_in[8];
    const float* wf1 = (const float*)d_in[9];
    const float* bf1 = (const float*)d_in[10];
    const float* g2  = (const float*)d_in[11];
    const float* be2 = (const float*)d_in[12];
    const float* wf2 = (const float*)d_in[13];
    const float* bf2 = (const float*)d_in[14];
    float* out = (float*)d_out;

    cudaFuncSetAttribute(k1mma, cudaFuncAttributeMaxDynamicSharedMemorySize, K1_SMEM_BYTES);
    cudaFuncSetAttribute(k3mma, cudaFuncAttributeMaxDynamicSharedMemorySize, K3_SMEM_BYTES);

    kinit<<<1, 128>>>();
    kprep<<<1, 128>>>(w0, b0, w1, b1);
    k1mma<<<B_N / SPB, 256, K1_SMEM_BYTES>>>(x, wc, bc);
    k2<<<1, 64>>>(g1, be1);
    kzerof<<<B_N * H1D / 256, 256>>>(bf1);
    k3mma<<<dim3(B_N / 128, NCHUNK), 256, K3_SMEM_BYTES>>>(wf1);
    k3stats<<<B_N / 128, 256>>>();
    k4<<<1, 64>>>(g2, be2);
    k5<<<B_N / 8, 256>>>(wf2, bf2, out);
}

// round 10
// speedup vs baseline: 1.3035x; 1.2443x over previous
#include <cuda_runtime.h>
#include <cstdint>

#define B_N   32768
#define C_INN 14
#define NN    52
#define H1D   64
#define H2D   128
#define FDIM  (NN*H2D)   // 6656
#define EPSB  1e-5f
#define SPB   8
#define NCHUNK 4
#define KC    (FDIM/NCHUNK)     // 1664 floats per chunk
#define NKT_C (KC/32)           // 52 k-tiles per chunk

// ---------------- scratch ----------------------------------------------------
__device__ float d_W01[H2D * C_INN];
__device__ float d_b01[H2D];
__device__ float d_Y[(size_t)B_N * NN * H2D];
__device__ float d_f[(size_t)B_N * H1D];
__device__ float d_sum1[NN], d_sq1[NN];
__device__ float d_sum2[H1D], d_sq2[H1D];
__device__ float d_a1[NN], d_c1[NN];
__device__ float d_a2[H1D], d_c2[H1D];

#define TF32R(o, f) asm("cvt.rna.tf32.f32 %0, %1;" : "=r"(o) : "f"(f))

__device__ __forceinline__ void mma_tf32(float c[4],
                                         uint32_t a0, uint32_t a1, uint32_t a2, uint32_t a3,
                                         uint32_t b0, uint32_t b1) {
    asm volatile(
        "mma.sync.aligned.m16n8k8.row.col.f32.tf32.tf32.f32 "
        "{%0,%1,%2,%3}, {%4,%5,%6,%7}, {%8,%9}, {%0,%1,%2,%3};"
        : "+f"(c[0]), "+f"(c[1]), "+f"(c[2]), "+f"(c[3])
        : "r"(a0), "r"(a1), "r"(a2), "r"(a3), "r"(b0), "r"(b1));
}

// ---------------- tiny kernels -----------------------------------------------
__global__ void ksetup(const float* __restrict__ w0, const float* __restrict__ b0,
                       const float* __restrict__ w1, const float* __restrict__ b1) {
    int t = threadIdx.x;
    if (t < NN)  { d_sum1[t] = 0.f; d_sq1[t] = 0.f; }
    if (t < H1D) { d_sum2[t] = 0.f; d_sq2[t] = 0.f; }
    int l = t;
    if (l < H2D) {
        float bb = b1[l];
        for (int m = 0; m < H1D; m++) bb = fmaf(w1[l*H1D + m], b0[m], bb);
        d_b01[l] = bb;
        for (int j = 0; j < C_INN; j++) {
            float s = 0.f;
            for (int m = 0; m < H1D; m++) s = fmaf(w1[l*H1D + m], w0[m*C_INN + j], s);
            d_W01[l*C_INN + j] = s;
        }
    }
}
__global__ void k2(const float* __restrict__ g1, const float* __restrict__ be1) {
    int t = threadIdx.x;
    if (t < NN) {
        float inv = 1.f / ((float)B_N * (float)H2D);
        float mu  = d_sum1[t] * inv;
        float var = d_sq1[t] * inv - mu * mu;
        float a   = g1[t] * rsqrtf(var + EPSB);
        d_a1[t] = a; d_c1[t] = be1[t] - mu * a;
    }
}
__global__ void k4(const float* __restrict__ g2, const float* __restrict__ be2) {
    int t = threadIdx.x;
    if (t < H1D) {
        float inv = 1.f / (float)B_N;
        float mu  = d_sum2[t] * inv;
        float var = d_sq2[t] * inv - mu * mu;
        float a   = g2[t] * rsqrtf(var + EPSB);
        d_a2[t] = a; d_c2[t] = be2[t] - mu * a;
    }
}
__global__ void kzerof(const float* __restrict__ bf1) {
    size_t i = (size_t)blockIdx.x * 256 + threadIdx.x;
    d_f[i] = bf1[i & 63];
}
__global__ void k3stats() {
    __shared__ float rs[2][4][64];
    const int t = threadIdx.x;
    const int col = t & 63, sub = t >> 6;
    const size_t r0 = (size_t)blockIdx.x * 128 + sub * 32;
    float s = 0.f, q = 0.f;
    #pragma unroll 4
    for (int i = 0; i < 32; i++) {
        float v = d_f[(r0 + i) * H1D + col];
        s += v; q = fmaf(v, v, q);
    }
    rs[0][sub][col] = s; rs[1][sub][col] = q;
    __syncthreads();
    if (sub == 0) {
        s = rs[0][0][col] + rs[0][1][col] + rs[0][2][col] + rs[0][3][col];
        q = rs[1][0][col] + rs[1][1][col] + rs[1][2][col] + rs[1][3][col];
        atomicAdd(&d_sum2[col], s);
        atomicAdd(&d_sq2[col], q);
    }
}

// ---------------- K1: stage1 tf32 mma -> Ht; stage2 tf32 mma -> Y -------------
// smem float offsets
#define HT_OFF   0                       // Ht[128][72] | stage[64][132] alias
#define WF_OFF   (128*72)                // Wf: 7ks x 7nt x 32 lanes float2 = 3136 floats
#define XS_OFF   (WF_OFF + 49*32*2)      // Xs[64][20]
#define BC_OFF   (XS_OFF + 64*20)        // [64]
#define K1_SMEM_FLOATS (BC_OFF + 64)
#define K1_SMEM_BYTES  (K1_SMEM_FLOATS * 4)

__global__ __launch_bounds__(256)
void k1mma(const float* __restrict__ x, const float* __restrict__ wc,
           const float* __restrict__ bc) {
    extern __shared__ __align__(16) float sm[];
    const int t = threadIdx.x;
    const int w = t >> 5, lane = t & 31;
    const int gid = lane >> 2, tig = lane & 3;
    const int lr0 = w * 16 + gid, lr1 = lr0 + 8;

    // ---- one-time fills ----
    // Wf in fragment order: Wf[(ks*7+nt)*32 + lane] = { wc[o][c0], wc[o][c1] }
    // o = nt*8+gid, c0 = ks*8+tig, c1 = c0+4; zero outside 52x52
    for (int i = t; i < 49 * 32; i += 256) {
        int ksnt = i >> 5, ln = i & 31;
        int ks = ksnt / 7, nt = ksnt - ks * 7;
        int g = ln >> 2, tg = ln & 3;
        int o = nt * 8 + g;
        int c0 = ks * 8 + tg, c1 = c0 + 4;
        float v0 = (o < NN) ? wc[o * NN + c0] : 0.f;            // c0 <= 51 always
        float v1 = (o < NN && c1 < NN) ? wc[o * NN + c1] : 0.f;
        uint32_t r0_, r1_;
        TF32R(r0_, v0); TF32R(r1_, v1);
        sm[WF_OFF + i * 2]     = __uint_as_float(r0_);
        sm[WF_OFF + i * 2 + 1] = __uint_as_float(r1_);
    }
    for (int i = t; i < 64 * 20; i += 256) sm[XS_OFF + i] = 0.f;
    if (t < 64)  sm[BC_OFF + t] = (t < NN) ? bc[t] : 0.f;

    // hoisted stage-1 A fragments (W01, tf32)
    uint32_t wf[2][4];
    #pragma unroll
    for (int ks = 0; ks < 2; ks++) {
        int j0 = ks * 8 + tig, j1 = j0 + 4;
        float v0 = d_W01[lr0 * C_INN + j0];
        float v1 = d_W01[lr1 * C_INN + j0];
        float v2 = (j1 < C_INN) ? d_W01[lr0 * C_INN + j1] : 0.f;
        float v3 = (j1 < C_INN) ? d_W01[lr1 * C_INN + j1] : 0.f;
        TF32R(wf[ks][0], v0); TF32R(wf[ks][1], v1);
        TF32R(wf[ks][2], v2); TF32R(wf[ks][3], v3);
    }
    const float bias0 = d_b01[lr0], bias1 = d_b01[lr1];
    __syncthreads();

    float sqs[8], sqq[8];
    #pragma unroll
    for (int i = 0; i < 8; i++) { sqs[i] = 0.f; sqq[i] = 0.f; }

    const size_t base = (size_t)blockIdx.x * SPB;
    for (int sp = 0; sp < SPB; sp++) {
        const size_t b = base + sp;
        const float* xb = x + b * (C_INN * NN);
        for (int i = t; i < C_INN * NN; i += 256) {
            int j = i / NN, n = i - j * NN;
            sm[XS_OFF + n * 20 + j] = xb[i];
        }
        __syncthreads();

        // ---- stage 1: Ht[l][c] = relu(W01 @ X^T + b01), c padded to 56 ----
        {
            float acc1[7][4];
            #pragma unroll
            for (int nt = 0; nt < 7; nt++)
                #pragma unroll
                for (int a = 0; a < 4; a++) acc1[nt][a] = 0.f;
            #pragma unroll
            for (int ks = 0; ks < 2; ks++) {
                #pragma unroll
                for (int nt = 0; nt < 7; nt++) {
                    int brow = nt * 8 + gid;
                    uint32_t b0 = __float_as_uint(sm[XS_OFF + brow * 20 + ks * 8 + tig]);
                    uint32_t b1 = __float_as_uint(sm[XS_OFF + brow * 20 + ks * 8 + tig + 4]);
                    mma_tf32(acc1[nt], wf[ks][0], wf[ks][1], wf[ks][2], wf[ks][3], b0, b1);
                }
            }
            #pragma unroll
            for (int nt = 0; nt < 7; nt++) {
                int c0 = nt * 8 + tig * 2;
                float h0 = fmaxf(acc1[nt][0] + bias0, 0.f);
                float h1 = fmaxf(acc1[nt][1] + bias0, 0.f);
                float h2 = fmaxf(acc1[nt][2] + bias1, 0.f);
                float h3 = fmaxf(acc1[nt][3] + bias1, 0.f);
                if (c0 >= NN) { h0 = h1 = h2 = h3 = 0.f; }
                uint32_t r0_, r1_, r2_, r3_;
                TF32R(r0_, h0); TF32R(r1_, h1); TF32R(r2_, h2); TF32R(r3_, h3);
                float2 p0 = { __uint_as_float(r0_), __uint_as_float(r1_) };
                float2 p1 = { __uint_as_float(r2_), __uint_as_float(r3_) };
                *(float2*)&sm[HT_OFF + lr0 * 72 + c0] = p0;
                *(float2*)&sm[HT_OFF + lr1 * 72 + c0] = p1;
            }
        }
        __syncthreads();

        // ---- stage 2: Yt[l][o] = Ht[l][c] @ wc^T, K=56, N=56 ----
        float acc2[7][4];
        #pragma unroll
        for (int nt = 0; nt < 7; nt++)
            #pragma unroll
            for (int a = 0; a < 4; a++) acc2[nt][a] = 0.f;
        #pragma unroll
        for (int ks = 0; ks < 7; ks++) {
            const int kc = ks * 8 + tig;
            uint32_t a0 = __float_as_uint(sm[HT_OFF + lr0 * 72 + kc]);
            uint32_t a1 = __float_as_uint(sm[HT_OFF + lr1 * 72 + kc]);
            uint32_t a2 = __float_as_uint(sm[HT_OFF + lr0 * 72 + kc + 4]);
            uint32_t a3 = __float_as_uint(sm[HT_OFF + lr1 * 72 + kc + 4]);
            #pragma unroll
            for (int nt = 0; nt < 7; nt++) {
                float2 bp = *(const float2*)&sm[WF_OFF + ((ks * 7 + nt) * 32 + lane) * 2];
                mma_tf32(acc2[nt], a0, a1, a2, a3,
                         __float_as_uint(bp.x), __float_as_uint(bp.y));
            }
        }
        __syncthreads();

        // ---- epilogue 2: +bc, transpose into stage[o][132] ----
        #pragma unroll
        for (int nt = 0; nt < 7; nt++) {
            int o0 = nt * 8 + tig * 2;
            float b0v = sm[BC_OFF + o0], b1v = sm[BC_OFF + o0 + 1];
            sm[HT_OFF + o0 * 132 + lr0]       = acc2[nt][0] + b0v;
            sm[HT_OFF + (o0 + 1) * 132 + lr0] = acc2[nt][1] + b1v;
            sm[HT_OFF + o0 * 132 + lr1]       = acc2[nt][2] + b0v;
            sm[HT_OFF + (o0 + 1) * 132 + lr1] = acc2[nt][3] + b1v;
        }
        __syncthreads();

        // ---- readout: coalesced Y store + bn1 partials ----
        float* yb = d_Y + b * FDIM;
        #pragma unroll
        for (int i = 0; i < 8; i++) {
            int o = w * 8 + i;
            if (o < NN) {
                float4 v = *(const float4*)&sm[HT_OFF + o * 132 + lane * 4];
                *(float4*)&yb[o * 128 + lane * 4] = v;
                sqs[i] += v.x + v.y + v.z + v.w;
                sqq[i] = fmaf(v.x, v.x, sqq[i]);
                sqq[i] = fmaf(v.y, v.y, sqq[i]);
                sqq[i] = fmaf(v.z, v.z, sqq[i]);
                sqq[i] = fmaf(v.w, v.w, sqq[i]);
            }
        }
    }

    #pragma unroll
    for (int i = 0; i < 8; i++) {
        float s = sqs[i], q = sqq[i];
        #pragma unroll
        for (int d = 16; d >= 1; d >>= 1) {
            s += __shfl_xor_sync(0xffffffffu, s, d);
            q += __shfl_xor_sync(0xffffffffu, q, d);
        }
        int o = w * 8 + i;
        if (lane == 0 && o < NN) {
            atomicAdd(&d_sum1[o], s);
            atomicAdd(&d_sq1[o], q);
        }
    }
}

// ---------------- K3: tf32 mma GEMM, split-K x4, frag-ordered B ---------------
// smem floats: A0[128][36] @0, A1 @4608, Bf0 (4ks x 8nt x 32 float2 = 2048 f) @9216, Bf1 @11264
#define K3A0 0
#define K3A1 4608
#define K3B0 9216
#define K3B1 11264
#define K3_SMEM_BYTES ((11264 + 2048) * 4)   // 53248

__global__ __launch_bounds__(256)
void k3mma(const float* __restrict__ wf1) {
    extern __shared__ __align__(16) float sm[];
    __shared__ float a1_s[NN], c1_s[NN];

    const int t = threadIdx.x;
    const int w = t >> 5, lane = t & 31;
    const int gid = lane >> 2, tig = lane & 3;
    if (t < NN) { a1_s[t] = d_a1[t]; c1_s[t] = d_c1[t]; }
    __syncthreads();

    const size_t b0 = (size_t)blockIdx.x * 128;
    const int chunk = blockIdx.y;
    const int kbase = chunk * KC;
    const int obase = chunk * (NN / NCHUNK);

    const int am = t >> 1, ah = t & 1;
    const float* Arow = d_Y + (b0 + am) * FDIM + kbase + ah * 16;
    const int bn = t >> 2, bq = t & 3;                  // row j, ks-quarter
    const float* Brow = wf1 + (size_t)bn * FDIM + kbase + bq * 8;
    // frag-order B write base (float2 index): (ks*8 + nt)*32 + gid*4 ; here ks=bq, nt=bn>>3, gid=bn&7
    const int bf_base2 = ((bq * 8 + (bn >> 3)) * 32 + (bn & 7) * 4);

    const int aoff[2] = { K3A0, K3A1 };
    const int boff[2] = { K3B0, K3B1 };

    float acc[8][4];
    #pragma unroll
    for (int nt = 0; nt < 8; nt++)
        #pragma unroll
        for (int i = 0; i < 4; i++) acc[nt][i] = 0.f;

    const int arow_lo = w * 16 + gid;
    const int arow_hi = arow_lo + 8;

    float4 aR[4], bR[2];

    #define K3_LDG(k0) do { \
        _Pragma("unroll") \
        for (int i = 0; i < 4; i++) aR[i] = *(const float4*)(Arow + (k0) + i * 4); \
        _Pragma("unroll") \
        for (int i = 0; i < 2; i++) bR[i] = *(const float4*)(Brow + (k0) + i * 4); \
    } while (0)

    #define K3_STS(s, k0) do { \
        const int _o = obase + ((k0) >> 7); \
        const float _a1 = a1_s[_o], _c1 = c1_s[_o]; \
        _Pragma("unroll") \
        for (int i = 0; i < 4; i++) { \
            float4 v = aR[i]; \
            uint32_t r0_, r1_, r2_, r3_; \
            TF32R(r0_, fmaxf(fmaf(_a1, v.x, _c1), 0.f)); \
            TF32R(r1_, fmaxf(fmaf(_a1, v.y, _c1), 0.f)); \
            TF32R(r2_, fmaxf(fmaf(_a1, v.z, _c1), 0.f)); \
            TF32R(r3_, fmaxf(fmaf(_a1, v.w, _c1), 0.f)); \
            float4 sv = { __uint_as_float(r0_), __uint_as_float(r1_), \
                          __uint_as_float(r2_), __uint_as_float(r3_) }; \
            *(float4*)&sm[aoff[s] + am * 36 + ah * 16 + i * 4] = sv; \
        } \
        { \
            uint32_t u0,u1,u2,u3,u4,u5,u6,u7; \
            TF32R(u0, bR[0].x); TF32R(u1, bR[0].y); TF32R(u2, bR[0].z); TF32R(u3, bR[0].w); \
            TF32R(u4, bR[1].x); TF32R(u5, bR[1].y); TF32R(u6, bR[1].z); TF32R(u7, bR[1].w); \
            float4 s0 = { __uint_as_float(u0), __uint_as_float(u4), \
                          __uint_as_float(u1), __uint_as_float(u5) }; \
            float4 s1 = { __uint_as_float(u2), __uint_as_float(u6), \
                          __uint_as_float(u3), __uint_as_float(u7) }; \
            *(float4*)&sm[boff[s] + bf_base2 * 2]     = s0; \
            *(float4*)&sm[boff[s] + bf_base2 * 2 + 4] = s1; \
        } \
    } while (0)

    K3_LDG(0);
    K3_STS(0, 0);
    K3_LDG(32);
    __syncthreads();

    for (int it = 0; it < NKT_C; it++) {
        const int cur = it & 1;
        if (it + 1 < NKT_C) K3_STS(cur ^ 1, (it + 1) * 32);
        if (it + 2 < NKT_C) K3_LDG((it + 2) * 32);
        const int ab = aoff[cur], bb = boff[cur];
        #pragma unroll
        for (int ks = 0; ks < 4; ks++) {
            const int kc = ks * 8 + tig;
            uint32_t a0 = __float_as_uint(sm[ab + arow_lo * 36 + kc]);
            uint32_t a1 = __float_as_uint(sm[ab + arow_hi * 36 + kc]);
            uint32_t a2 = __float_as_uint(sm[ab + arow_lo * 36 + kc + 4]);
            uint32_t a3 = __float_as_uint(sm[ab + arow_hi * 36 + kc + 4]);
            #pragma unroll
            for (int nt = 0; nt < 8; nt++) {
                float2 bp = *(const float2*)&sm[bb + ((ks * 8 + nt) * 32 + lane) * 2];
                mma_tf32(acc[nt], a0, a1, a2, a3,
                         __float_as_uint(bp.x), __float_as_uint(bp.y));
            }
        }
        __syncthreads();
    }

    // epilogue: atomic-accumulate partial fc1 sums into d_f (base = bf1)
    #pragma unroll
    for (int nt = 0; nt < 8; nt++) {
        const int n0 = nt * 8 + tig * 2;
        float* f_lo = d_f + (b0 + arow_lo) * H1D + n0;
        float* f_hi = d_f + (b0 + arow_hi) * H1D + n0;
        atomicAdd(f_lo,     acc[nt][0]);
        atomicAdd(f_lo + 1, acc[nt][1]);
        atomicAdd(f_hi,     acc[nt][2]);
        atomicAdd(f_hi + 1, acc[nt][3]);
    }
}

// ---------------- K5 ----------------------------------------------------------
__global__ void k5(const float* __restrict__ wf2, const float* __restrict__ bf2,
                   float* __restrict__ out) {
    const int t = threadIdx.x;
    const int w = t >> 5, l = t & 31;
    const size_t b = (size_t)blockIdx.x * 8 + w;
    float f0 = d_f[b * H1D + l];
    float f1 = d_f[b * H1D + 32 + l];
    float z0 = fmaxf(fmaf(d_a2[l], f0, d_c2[l]), 0.f);
    float z1 = fmaxf(fmaf(d_a2[32 + l], f1, d_c2[32 + l]), 0.f);
    float p0 = fmaf(z0, wf2[l],      z1 * wf2[32 + l]);
    float p1 = fmaf(z0, wf2[64 + l], z1 * wf2[96 + l]);
    #pragma unroll
    for (int d = 16; d >= 1; d >>= 1) {
        p0 += __shfl_xor_sync(0xffffffffu, p0, d);
        p1 += __shfl_xor_sync(0xffffffffu, p1, d);
    }
    if (l == 0) {
        out[b * 2 + 0] = p0 + bf2[0];
        out[b * 2 + 1] = p1 + bf2[1];
    }
}

// ---------------- launch -------------------------------------------------------
extern "C" void kernel_launch(void* const* d_in, const int* in_sizes, int n_in,
                              void* d_out, int out_size) {
    const float* x   = (const float*)d_in[0];
    const float* w0  = (const float*)d_in[1];
    const float* b0  = (const float*)d_in[2];
    const float* w1  = (const float*)d_in[3];
    const float* b1  = (const float*)d_in[4];
    const float* wc  = (const float*)d_in[5];
    const float* bc  = (const float*)d_in[6];
    const float* g1  = (const float*)d_in[7];
    const float* be1 = (const float*)d_in[8];
    const float* wf1 = (const float*)d_in[9];
    const float* bf1 = (const float*)d_in[10];
    const float* g2  = (const float*)d_in[11];
    const float* be2 = (const float*)d_in[12];
    const float* wf2 = (const float*)d_in[13];
    const float* bf2 = (const float*)d_in[14];
    float* out = (float*)d_out;

    cudaFuncSetAttribute(k1mma, cudaFuncAttributeMaxDynamicSharedMemorySize, K1_SMEM_BYTES);
    cudaFuncSetAttribute(k3mma, cudaFuncAttributeMaxDynamicSharedMemorySize, K3_SMEM_BYTES);

    ksetup<<<1, 128>>>(w0, b0, w1, b1);
    k1mma<<<B_N / SPB, 256, K1_SMEM_BYTES>>>(x, wc, bc);
    k2<<<1, 64>>>(g1, be1);
    kzerof<<<B_N * H1D / 256, 256>>>(bf1);
    k3mma<<<dim3(B_N / 128, NCHUNK), 256, K3_SMEM_BYTES>>>(wf1);
    k3stats<<<B_N / 128, 256>>>();
    k4<<<1, 64>>>(g2, be2);
    k5<<<B_N / 8, 256>>>(wf2, bf2, out);
}